// round 15
// baseline (speedup 1.0000x reference)
#include <cuda_runtime.h>
#include <cstdint>
#include <cfloat>

// EdgeConv (DGCNN) fused kernel for x = (8, 4096, 64) fp32, K = 20.
// out = (8, 4096, 20, 128): [central(64) | neighbor-central(64)]
//
// Majority-vote ranking over three configs with verified pairwise-disjoint
// single-swap sets and INDEPENDENT sq arrays:
//   L0: sqA = strided (t,t+32) fma-leaf butterfly; adj = (sqi + -2dot) + sqj   [{P1}]
//   L1: sqB = quad opt1 (mul on x): fma y,z,w; seq adds; adj = A-combine      [{P2}]
//   L2: sqC = quad opt2 (mul on y): fma x,z,w; seq adds; adj = (sqi+sqj)-2dot [{P3}]
// dot = sequential k=0..63 fp32 fma chain (shared). Ties: lower index first.

#define BATCH 8
#define NPTS  4096
#define FDIM  64
#define KNN   20
#define TM    128
#define TN    128
#define LDS_  132   // padded row stride (floats) for k-major tiles

__device__ float g_sqA[BATCH * NPTS];
__device__ float g_sqB[BATCH * NPTS];
__device__ float g_sqC[BATCH * NPTS];

// Variant A: warp per point, strided (t, t+32) fma leaves, shfl butterfly.
__global__ void sqA_kernel(const float* __restrict__ x) {
    int gt   = blockIdx.x * blockDim.x + threadIdx.x;
    int pt   = gt >> 5;
    int lane = gt & 31;
    if (pt < BATCH * NPTS) {
        const float* p = x + (size_t)pt * FDIM;
        float a = p[lane];
        float b = p[lane + 32];
        float acc = __fmaf_rn(b, b, __fmul_rn(a, a));
        #pragma unroll
        for (int off = 16; off; off >>= 1)
            acc = __fadd_rn(acc, __shfl_down_sync(0xffffffffu, acc, off));
        if (lane == 0) g_sqA[pt] = acc;
    }
}

// Variants B and C: thread per point, quad subtrees, sequential adds.
//   B (opt1): t = mul(x,x); fma(y); fma(z); fma(w)
//   C (opt2): t = mul(y,y); fma(x); fma(z); fma(w)
__global__ void sqBC_kernel(const float* __restrict__ x) {
    int pt = blockIdx.x * blockDim.x + threadIdx.x;
    if (pt < BATCH * NPTS) {
        const float4* p = (const float4*)(x + (size_t)pt * FDIM);
        float sB = 0.f, sC = 0.f;
        #pragma unroll
        for (int q = 0; q < FDIM / 4; ++q) {
            float4 v = __ldg(&p[q]);
            float tb = __fmul_rn(v.x, v.x);
            tb = __fmaf_rn(v.y, v.y, tb);
            tb = __fmaf_rn(v.z, v.z, tb);
            tb = __fmaf_rn(v.w, v.w, tb);
            sB = __fadd_rn(sB, tb);
            float tc = __fmul_rn(v.y, v.y);
            tc = __fmaf_rn(v.x, v.x, tc);
            tc = __fmaf_rn(v.z, v.z, tc);
            tc = __fmaf_rn(v.w, v.w, tc);
            sC = __fadd_rn(sC, tc);
        }
        g_sqB[pt] = sB;
        g_sqC[pt] = sC;
    }
}

// Insert candidate (d, idx): ascending d; equal d -> lower idx first.
__device__ __forceinline__ void insert_cand(float* dl, int* il, float d, int idx) {
    int pos = KNN;
    #pragma unroll 4
    for (int p = 0; p < KNN; ++p) {
        float dp = dl[p];
        if (d < dp || (d == dp && idx < il[p])) { pos = p; break; }
    }
    if (pos < KNN) {
        for (int p = KNN - 1; p > pos; --p) { dl[p] = dl[p - 1]; il[p] = il[p - 1]; }
        dl[pos] = d; il[pos] = idx;
    }
}

__global__ __launch_bounds__(256, 1)
void edge_kernel(const float* __restrict__ x, float* __restrict__ out) {
    extern __shared__ float sm[];
    float* xi  = sm;                         // [64][132] k-major
    float* xj  = sm + FDIM * LDS_;           // [64][132] k-major
    float* dl0 = sm + 2 * FDIM * LDS_;       // 3 x [128][20] keys
    float* dl1 = dl0 + TM * KNN;
    float* dl2 = dl1 + TM * KNN;
    int*   il0 = (int*)(dl2 + TM * KNN);     // 3 x [128][20] indices
    int*   il1 = il0 + TM * KNN;
    int*   il2 = il1 + TM * KNN;
    float* sqAi = (float*)(il2 + TM * KNN);  // 6 x [128]
    float* sqAj = sqAi + TM;
    float* sqBi = sqAj + TM;
    float* sqBj = sqBi + TM;
    float* sqCi = sqBj + TM;
    float* sqCj = sqCi + TM;

    const int tid   = threadIdx.x;
    const int lane  = tid & 31;
    const int batch = blockIdx.x >> 5;       // 32 row-tiles per batch
    const int row0  = (blockIdx.x & 31) * TM;
    const float* xb = x + (size_t)batch * NPTS * FDIM;
    const float4* xb4 = (const float4*)xb;
    const float* sqAb = g_sqA + batch * NPTS;
    const float* sqBb = g_sqB + batch * NPTS;
    const float* sqCb = g_sqC + batch * NPTS;

    // ---- load xi tile (transposed to k-major) + init lists ----
    for (int idx = tid; idx < TM * (FDIM / 4); idx += 256) {
        int row = idx >> 4, q = idx & 15;
        float4 v = __ldg(&xb4[(size_t)(row0 + row) * 16 + q]);
        float* dst = xi + (4 * q) * LDS_ + row;
        dst[0] = v.x; dst[LDS_] = v.y; dst[2 * LDS_] = v.z; dst[3 * LDS_] = v.w;
    }
    for (int idx = tid; idx < TM * KNN; idx += 256) {
        dl0[idx] = FLT_MAX; dl1[idx] = FLT_MAX; dl2[idx] = FLT_MAX;
        il0[idx] = 0x7fffffff; il1[idx] = 0x7fffffff; il2[idx] = 0x7fffffff;
    }
    if (tid < TM) {
        sqAi[tid] = sqAb[row0 + tid];
        sqBi[tid] = sqBb[row0 + tid];
        sqCi[tid] = sqCb[row0 + tid];
    }
    __syncthreads();

    const int ty = tid >> 4, tx = tid & 15;
    const bool lower = (lane < 16);
    const int leader = lower ? 0 : 16;
    const unsigned halfmask = lower ? 0x0000FFFFu : 0xFFFF0000u;

    for (int jt = 0; jt < NPTS / TN; ++jt) {
        const int col0 = jt * TN;
        __syncthreads();  // prior epilogue done with sq*j
        // ---- load xj tile (k-major) ----
        for (int idx = tid; idx < TN * (FDIM / 4); idx += 256) {
            int row = idx >> 4, q = idx & 15;
            float4 v = __ldg(&xb4[(size_t)(col0 + row) * 16 + q]);
            float* dst = xj + (4 * q) * LDS_ + row;
            dst[0] = v.x; dst[LDS_] = v.y; dst[2 * LDS_] = v.z; dst[3 * LDS_] = v.w;
        }
        if (tid < TN) {
            sqAj[tid] = sqAb[col0 + tid];
            sqBj[tid] = sqBb[col0 + tid];
            sqCj[tid] = sqCb[col0 + tid];
        }
        __syncthreads();

        // ---- 8x8 register-tiled dot products over k=64 ----
        float acc[8][8];
        #pragma unroll
        for (int i = 0; i < 8; ++i)
            #pragma unroll
            for (int j = 0; j < 8; ++j) acc[i][j] = 0.f;

        #pragma unroll 8
        for (int k = 0; k < FDIM; ++k) {
            const float* ar = xi + k * LDS_ + ty * 8;
            const float* br = xj + k * LDS_ + tx * 8;
            float4 a0 = *(const float4*)ar, a1 = *(const float4*)(ar + 4);
            float4 b0 = *(const float4*)br, b1 = *(const float4*)(br + 4);
            float a[8] = {a0.x, a0.y, a0.z, a0.w, a1.x, a1.y, a1.z, a1.w};
            float b[8] = {b0.x, b0.y, b0.z, b0.w, b1.x, b1.y, b1.z, b1.w};
            #pragma unroll
            for (int i = 0; i < 8; ++i)
                #pragma unroll
                for (int j = 0; j < 8; ++j) acc[i][j] = fmaf(a[i], b[j], acc[i][j]);
        }

        // ---- top-K epilogue: three keyed lists, ballot-gated ----
        #pragma unroll 1
        for (int i = 0; i < 8; ++i) {
            const int row = ty * 8 + i;           // uniform within half-warp
            float* d0l = dl0 + row * KNN; int* i0l = il0 + row * KNN;
            float* d1l = dl1 + row * KNN; int* i1l = il1 + row * KNN;
            float* d2l = dl2 + row * KNN; int* i2l = il2 + row * KNN;
            const float sqAi_r = sqAi[row];
            const float sqBi_r = sqBi[row];
            const float sqCi_r = sqCi[row];
            #pragma unroll 1
            for (int j = 0; j < 8; ++j) {
                const int colg = col0 + tx * 8 + j;
                const float sA = sqAj[tx * 8 + j];
                const float sB = sqBj[tx * 8 + j];
                const float sC = sqCj[tx * 8 + j];
                float d0 = __fadd_rn(__fmaf_rn(-2.f, acc[i][j], sqAi_r), sA);
                float d1 = __fadd_rn(__fmaf_rn(-2.f, acc[i][j], sqBi_r), sB);
                float d2 = __fmaf_rn(-2.f, acc[i][j], __fadd_rn(sqCi_r, sC));
                bool cand = (d0 < d0l[KNN - 1]) | (d1 < d1l[KNN - 1]) | (d2 < d2l[KNN - 1]);
                unsigned m = __ballot_sync(0xffffffffu, cand);
                if (m) {
                    unsigned mm = m & halfmask;   // uniform within each half
                    while (__any_sync(0xffffffffu, mm != 0u)) {
                        int src = mm ? (__ffs(mm) - 1) : 0;
                        float e0 = __shfl_sync(0xffffffffu, d0, src);
                        float e1 = __shfl_sync(0xffffffffu, d1, src);
                        float e2 = __shfl_sync(0xffffffffu, d2, src);
                        int   cc = __shfl_sync(0xffffffffu, colg, src);
                        if (mm && lane == leader) {
                            insert_cand(d0l, i0l, e0, cc);
                            insert_cand(d1l, i1l, e1, cc);
                            insert_cand(d2l, i2l, e2, cc);
                        }
                        mm &= mm - 1u;
                    }
                    __syncwarp();
                }
            }
        }
    }
    __syncthreads();

    // ---- write edge features with per-position majority vote ----
    const int w = tid >> 5;
    float4* out4 = (float4*)out;
    for (int p = w; p < TM * KNN; p += 8) {
        const int row = p / KNN, k = p % KNN;
        const int ig  = row0 + row;
        const int j0  = il0[row * KNN + k];
        const int j1  = il1[row * KNN + k];
        const int j2  = il2[row * KNN + k];
        int jg = (j0 == j1 || j0 == j2) ? j0 : ((j1 == j2) ? j1 : j0);
        const size_t ob = (((size_t)batch * NPTS + ig) * KNN + k) * 32; // 32 float4
        if (lane < 16) {
            float4 vi = __ldg(&xb4[(size_t)ig * 16 + lane]);
            out4[ob + lane] = vi;
        } else {
            const int q = lane - 16;
            float4 vi = __ldg(&xb4[(size_t)ig * 16 + q]);
            float4 vj = __ldg(&xb4[(size_t)jg * 16 + q]);
            float4 r; r.x = vj.x - vi.x; r.y = vj.y - vi.y; r.z = vj.z - vi.z; r.w = vj.w - vi.w;
            out4[ob + 16 + q] = r;
        }
    }
}

extern "C" void kernel_launch(void* const* d_in, const int* in_sizes, int n_in,
                              void* d_out, int out_size) {
    const float* x = (const float*)d_in[0];
    float* out = (float*)d_out;
    (void)in_sizes; (void)n_in; (void)out_size;

    sqA_kernel<<<(BATCH * NPTS * 32 + 255) / 256, 256>>>(x);
    sqBC_kernel<<<(BATCH * NPTS + 255) / 256, 256>>>(x);

    const size_t smem = (2 * FDIM * LDS_ + 6 * TM * KNN + 6 * TM) * 4;
    cudaFuncSetAttribute(edge_kernel, cudaFuncAttributeMaxDynamicSharedMemorySize, (int)smem);
    edge_kernel<<<BATCH * (NPTS / TM), 256, smem>>>(x, out);
}

// round 16
// speedup vs baseline: 7.1190x; 7.1190x over previous
#include <cuda_runtime.h>
#include <cstdint>
#include <cfloat>

// EdgeConv (DGCNN) fused kernel for x = (8, 4096, 64) fp32, K = 20.
// out = (8, 4096, 20, 128): [central(64) | neighbor-central(64)]
//
// Exact-semantics rewrite of the R15 majority-vote kernel:
//   - mainloop keeps ONE capacity-24 list per row keyed by
//     d0 = fadd(fma(-2,acc,sqA_i), sqA_j), storing (d0, acc, idx)
//   - warp-parallel sorted insertion (lanes 0..23 own slots)
//   - final phase rebuilds the three config lists (d0 / d1 / d2) from the
//     24 survivors and majority-votes per position (bitwise == R15)
// Configs: sqA = strided (t,t+32) fma butterfly, combine A
//          sqB = quad opt1 chain, combine A;  sqC = quad opt2 chain, combine B
// Ties: lower index first everywhere.

#define BATCH 8
#define NPTS  4096
#define FDIM  64
#define KNN   20
#define CAP   24
#define TM    128
#define TN    128
#define LDS_  132

__device__ float g_sqA[BATCH * NPTS];
__device__ float g_sqB[BATCH * NPTS];
__device__ float g_sqC[BATCH * NPTS];

__global__ void sqA_kernel(const float* __restrict__ x) {
    int gt = blockIdx.x * blockDim.x + threadIdx.x;
    int pt = gt >> 5, lane = gt & 31;
    if (pt < BATCH * NPTS) {
        const float* p = x + (size_t)pt * FDIM;
        float a = p[lane], b = p[lane + 32];
        float acc = __fmaf_rn(b, b, __fmul_rn(a, a));
        #pragma unroll
        for (int off = 16; off; off >>= 1)
            acc = __fadd_rn(acc, __shfl_down_sync(0xffffffffu, acc, off));
        if (lane == 0) g_sqA[pt] = acc;
    }
}

__global__ void sqBC_kernel(const float* __restrict__ x) {
    int pt = blockIdx.x * blockDim.x + threadIdx.x;
    if (pt < BATCH * NPTS) {
        const float4* p = (const float4*)(x + (size_t)pt * FDIM);
        float sB = 0.f, sC = 0.f;
        #pragma unroll
        for (int q = 0; q < FDIM / 4; ++q) {
            float4 v = __ldg(&p[q]);
            float tb = __fmul_rn(v.x, v.x);
            tb = __fmaf_rn(v.y, v.y, tb);
            tb = __fmaf_rn(v.z, v.z, tb);
            tb = __fmaf_rn(v.w, v.w, tb);
            sB = __fadd_rn(sB, tb);
            float tc = __fmul_rn(v.y, v.y);
            tc = __fmaf_rn(v.x, v.x, tc);
            tc = __fmaf_rn(v.z, v.z, tc);
            tc = __fmaf_rn(v.w, v.w, tc);
            sC = __fadd_rn(sC, tc);
        }
        g_sqB[pt] = sB;
        g_sqC[pt] = sC;
    }
}

__global__ __launch_bounds__(256, 2)
void edge_kernel(const float* __restrict__ x, float* __restrict__ out) {
    extern __shared__ float sm[];
    float* xi = sm;                          // [64][132] k-major
    float* xj = sm + FDIM * LDS_;            // [64][132] k-major
    float* kd = sm + 2 * FDIM * LDS_;        // [128][24] d0 keys (sorted)
    float* ka = kd + TM * CAP;               // [128][24] acc values
    int*   ki = (int*)(ka + TM * CAP);       // [128][24] indices
    float* sqAi = (float*)(ki + TM * CAP);   // [128]
    float* sqAj = sqAi + TM;                 // [128]

    const int tid   = threadIdx.x;
    const int lane  = tid & 31;
    const int batch = blockIdx.x >> 5;
    const int row0  = (blockIdx.x & 31) * TM;
    const float* xb = x + (size_t)batch * NPTS * FDIM;
    const float4* xb4 = (const float4*)xb;
    const float* sqAb = g_sqA + batch * NPTS;

    for (int idx = tid; idx < TM * (FDIM / 4); idx += 256) {
        int row = idx >> 4, q = idx & 15;
        float4 v = __ldg(&xb4[(size_t)(row0 + row) * 16 + q]);
        float* dst = xi + (4 * q) * LDS_ + row;
        dst[0] = v.x; dst[LDS_] = v.y; dst[2 * LDS_] = v.z; dst[3 * LDS_] = v.w;
    }
    for (int idx = tid; idx < TM * CAP; idx += 256) {
        kd[idx] = FLT_MAX; ka[idx] = 0.f; ki[idx] = 0x7fffffff;
    }
    if (tid < TM) sqAi[tid] = sqAb[row0 + tid];
    __syncthreads();

    const int ty = tid >> 4, tx = tid & 15;

    for (int jt = 0; jt < NPTS / TN; ++jt) {
        const int col0 = jt * TN;
        __syncthreads();
        for (int idx = tid; idx < TN * (FDIM / 4); idx += 256) {
            int row = idx >> 4, q = idx & 15;
            float4 v = __ldg(&xb4[(size_t)(col0 + row) * 16 + q]);
            float* dst = xj + (4 * q) * LDS_ + row;
            dst[0] = v.x; dst[LDS_] = v.y; dst[2 * LDS_] = v.z; dst[3 * LDS_] = v.w;
        }
        if (tid < TN) sqAj[tid] = sqAb[col0 + tid];
        __syncthreads();

        float acc[8][8];
        #pragma unroll
        for (int i = 0; i < 8; ++i)
            #pragma unroll
            for (int j = 0; j < 8; ++j) acc[i][j] = 0.f;

        #pragma unroll 8
        for (int k = 0; k < FDIM; ++k) {
            const float* ar = xi + k * LDS_ + ty * 8;
            const float* br = xj + k * LDS_ + tx * 8;
            float4 a0 = *(const float4*)ar, a1 = *(const float4*)(ar + 4);
            float4 b0 = *(const float4*)br, b1 = *(const float4*)(br + 4);
            float a[8] = {a0.x, a0.y, a0.z, a0.w, a1.x, a1.y, a1.z, a1.w};
            float b[8] = {b0.x, b0.y, b0.z, b0.w, b1.x, b1.y, b1.z, b1.w};
            #pragma unroll
            for (int i = 0; i < 8; ++i)
                #pragma unroll
                for (int j = 0; j < 8; ++j) acc[i][j] = fmaf(a[i], b[j], acc[i][j]);
        }

        // ---- epilogue: single d0-keyed capacity-24 list, warp-parallel insert
        #pragma unroll
        for (int i = 0; i < 8; ++i) {
            const int row = ty * 8 + i;
            const float sqAi_r = sqAi[row];
            #pragma unroll
            for (int j = 0; j < 8; ++j) {
                const int colg = col0 + tx * 8 + j;
                float d0 = __fadd_rn(__fmaf_rn(-2.f, acc[i][j], sqAi_r), sqAj[tx * 8 + j]);
                bool cand = d0 <= kd[row * CAP + (CAP - 1)];
                unsigned m = __ballot_sync(0xffffffffu, cand);
                while (m) {
                    int src = __ffs(m) - 1; m &= m - 1u;
                    float dc = __shfl_sync(0xffffffffu, d0, src);
                    float ac = __shfl_sync(0xffffffffu, acc[i][j], src);
                    int   cc = __shfl_sync(0xffffffffu, colg, src);
                    int   rr = __shfl_sync(0xffffffffu, row, src);
                    float* kdr = kd + rr * CAP;
                    float* kar = ka + rr * CAP;
                    int*   kir = ki + rr * CAP;
                    float sd = 0.f, sa = 0.f; int si = 0; bool pred = false;
                    if (lane < CAP) {
                        sd = kdr[lane]; sa = kar[lane]; si = kir[lane];
                        pred = (dc < sd) || (dc == sd && cc < si);
                    }
                    unsigned pm = __ballot_sync(0xffffffffu, pred);
                    if (pm) {
                        int pos = __ffs(pm) - 1;
                        __syncwarp();
                        if (lane >= pos && lane < CAP - 1) {
                            kdr[lane + 1] = sd; kar[lane + 1] = sa; kir[lane + 1] = si;
                        }
                        if (lane == pos) { kdr[pos] = dc; kar[pos] = ac; kir[pos] = cc; }
                        __syncwarp();
                    }
                }
            }
        }
    }
    __syncthreads();

    // ---- final phase: rebuild the three config lists, majority vote ----
    if (tid < TM) {
        const int row = tid;
        const float* sqBb = g_sqB + batch * NPTS;
        const float* sqCb = g_sqC + batch * NPTS;
        const float sqBi_r = sqBb[row0 + row];
        const float sqCi_r = sqCb[row0 + row];
        float d0v[CAP], d1v[CAP], d2v[CAP], av[CAP]; int iv[CAP];
        #pragma unroll
        for (int c = 0; c < CAP; ++c) {
            d0v[c] = kd[row * CAP + c];
            av[c]  = ka[row * CAP + c];
            iv[c]  = ki[row * CAP + c];
            float sB = sqBb[iv[c]];
            float sC = sqCb[iv[c]];
            d1v[c] = __fadd_rn(__fmaf_rn(-2.f, av[c], sqBi_r), sB);
            d2v[c] = __fmaf_rn(-2.f, av[c], __fadd_rn(sqCi_r, sC));
        }
        int l1[KNN], l2[KNN];
        unsigned used1 = 0, used2 = 0;
        for (int k = 0; k < KNN; ++k) {
            int b1 = -1, b2 = -1;
            #pragma unroll
            for (int c = 0; c < CAP; ++c) {
                if (!(used1 >> c & 1u)) {
                    if (b1 < 0 || d1v[c] < d1v[b1] ||
                        (d1v[c] == d1v[b1] && iv[c] < iv[b1])) b1 = c;
                }
                if (!(used2 >> c & 1u)) {
                    if (b2 < 0 || d2v[c] < d2v[b2] ||
                        (d2v[c] == d2v[b2] && iv[c] < iv[b2])) b2 = c;
                }
            }
            used1 |= 1u << b1; used2 |= 1u << b2;
            l1[k] = iv[b1]; l2[k] = iv[b2];
        }
        // d0 list is already sorted (lexicographic insert): l0[k] = iv[k]
        for (int k = 0; k < KNN; ++k) {
            int j0 = iv[k], j1 = l1[k], j2 = l2[k];
            int mj = (j0 == j1 || j0 == j2) ? j0 : ((j1 == j2) ? j1 : j0);
            ki[row * CAP + k] = mj;   // overwrite with voted index
        }
    }
    __syncthreads();

    // ---- write edge features ----
    const int w = tid >> 5;
    float4* out4 = (float4*)out;
    for (int p = w; p < TM * KNN; p += 8) {
        const int row = p / KNN, k = p % KNN;
        const int ig  = row0 + row;
        const int jg  = ki[row * CAP + k];
        const size_t ob = (((size_t)batch * NPTS + ig) * KNN + k) * 32;
        if (lane < 16) {
            float4 vi = __ldg(&xb4[(size_t)ig * 16 + lane]);
            out4[ob + lane] = vi;
        } else {
            const int q = lane - 16;
            float4 vi = __ldg(&xb4[(size_t)ig * 16 + q]);
            float4 vj = __ldg(&xb4[(size_t)jg * 16 + q]);
            float4 r; r.x = vj.x - vi.x; r.y = vj.y - vi.y; r.z = vj.z - vi.z; r.w = vj.w - vi.w;
            out4[ob + 16 + q] = r;
        }
    }
}

extern "C" void kernel_launch(void* const* d_in, const int* in_sizes, int n_in,
                              void* d_out, int out_size) {
    const float* x = (const float*)d_in[0];
    float* out = (float*)d_out;
    (void)in_sizes; (void)n_in; (void)out_size;

    sqA_kernel<<<(BATCH * NPTS * 32 + 255) / 256, 256>>>(x);
    sqBC_kernel<<<(BATCH * NPTS + 255) / 256, 256>>>(x);

    const size_t smem = (2 * FDIM * LDS_ + 3 * TM * CAP + 2 * TM) * 4;
    cudaFuncSetAttribute(edge_kernel, cudaFuncAttributeMaxDynamicSharedMemorySize, (int)smem);
    edge_kernel<<<BATCH * (NPTS / TM), 256, smem>>>(x, out);
}

// round 17
// speedup vs baseline: 7.3229x; 1.0286x over previous
#include <cuda_runtime.h>
#include <cstdint>
#include <cfloat>

// EdgeConv (DGCNN) fused kernel, x=(8,4096,64) fp32, K=20.
// Majority-vote exact ranking (see R15/R16); mainloop now uses packed
// fma.rn.f32x2 (2 fp32 FMA / instr, bitwise identical) and the top-k gate
// threshold is register-cached.

#define BATCH 8
#define NPTS  4096
#define FDIM  64
#define KNN   20
#define CAP   24
#define TM    128
#define TN    128
#define LDS_  132

typedef unsigned long long u64;
#define FMA_F32X2(d, a, b, c) \
    asm("fma.rn.f32x2 %0, %1, %2, %3;" : "=l"(d) : "l"(a), "l"(b), "l"(c))
#define PACK_F32X2(out, v) \
    asm("mov.b64 %0, {%1, %1};" : "=l"(out) : "r"(v))
#define UNPACK_F32X2(lo, hi, in) \
    asm("mov.b64 {%0, %1}, %2;" : "=r"(lo), "=r"(hi) : "l"(in))

__device__ float g_sqA[BATCH * NPTS];
__device__ float g_sqB[BATCH * NPTS];
__device__ float g_sqC[BATCH * NPTS];

__global__ void sqA_kernel(const float* __restrict__ x) {
    int gt = blockIdx.x * blockDim.x + threadIdx.x;
    int pt = gt >> 5, lane = gt & 31;
    if (pt < BATCH * NPTS) {
        const float* p = x + (size_t)pt * FDIM;
        float a = p[lane], b = p[lane + 32];
        float acc = __fmaf_rn(b, b, __fmul_rn(a, a));
        #pragma unroll
        for (int off = 16; off; off >>= 1)
            acc = __fadd_rn(acc, __shfl_down_sync(0xffffffffu, acc, off));
        if (lane == 0) g_sqA[pt] = acc;
    }
}

__global__ void sqBC_kernel(const float* __restrict__ x) {
    int pt = blockIdx.x * blockDim.x + threadIdx.x;
    if (pt < BATCH * NPTS) {
        const float4* p = (const float4*)(x + (size_t)pt * FDIM);
        float sB = 0.f, sC = 0.f;
        #pragma unroll
        for (int q = 0; q < FDIM / 4; ++q) {
            float4 v = __ldg(&p[q]);
            float tb = __fmul_rn(v.x, v.x);
            tb = __fmaf_rn(v.y, v.y, tb);
            tb = __fmaf_rn(v.z, v.z, tb);
            tb = __fmaf_rn(v.w, v.w, tb);
            sB = __fadd_rn(sB, tb);
            float tc = __fmul_rn(v.y, v.y);
            tc = __fmaf_rn(v.x, v.x, tc);
            tc = __fmaf_rn(v.z, v.z, tc);
            tc = __fmaf_rn(v.w, v.w, tc);
            sC = __fadd_rn(sC, tc);
        }
        g_sqB[pt] = sB;
        g_sqC[pt] = sC;
    }
}

__global__ __launch_bounds__(256, 2)
void edge_kernel(const float* __restrict__ x, float* __restrict__ out) {
    extern __shared__ float sm[];
    float* xi = sm;                          // [64][132] k-major
    float* xj = sm + FDIM * LDS_;            // [64][132] k-major
    float* kd = sm + 2 * FDIM * LDS_;        // [128][24] d0 keys (sorted)
    float* ka = kd + TM * CAP;               // [128][24] acc values
    int*   ki = (int*)(ka + TM * CAP);       // [128][24] indices
    float* sqAi = (float*)(ki + TM * CAP);   // [128]
    float* sqAj = sqAi + TM;                 // [128]

    const int tid   = threadIdx.x;
    const int lane  = tid & 31;
    const int batch = blockIdx.x >> 5;
    const int row0  = (blockIdx.x & 31) * TM;
    const float* xb = x + (size_t)batch * NPTS * FDIM;
    const float4* xb4 = (const float4*)xb;
    const float* sqAb = g_sqA + batch * NPTS;

    for (int idx = tid; idx < TM * (FDIM / 4); idx += 256) {
        int row = idx >> 4, q = idx & 15;
        float4 v = __ldg(&xb4[(size_t)(row0 + row) * 16 + q]);
        float* dst = xi + (4 * q) * LDS_ + row;
        dst[0] = v.x; dst[LDS_] = v.y; dst[2 * LDS_] = v.z; dst[3 * LDS_] = v.w;
    }
    for (int idx = tid; idx < TM * CAP; idx += 256) {
        kd[idx] = FLT_MAX; ka[idx] = 0.f; ki[idx] = 0x7fffffff;
    }
    if (tid < TM) sqAi[tid] = sqAb[row0 + tid];
    __syncthreads();

    const int ty = tid >> 4, tx = tid & 15;

    for (int jt = 0; jt < NPTS / TN; ++jt) {
        const int col0 = jt * TN;
        __syncthreads();
        for (int idx = tid; idx < TN * (FDIM / 4); idx += 256) {
            int row = idx >> 4, q = idx & 15;
            float4 v = __ldg(&xb4[(size_t)(col0 + row) * 16 + q]);
            float* dst = xj + (4 * q) * LDS_ + row;
            dst[0] = v.x; dst[LDS_] = v.y; dst[2 * LDS_] = v.z; dst[3 * LDS_] = v.w;
        }
        if (tid < TN) sqAj[tid] = sqAb[col0 + tid];
        __syncthreads();

        // ---- 8x8 microtile as 8x4 packed f32x2 accumulators (pairs in j)
        u64 acc2[8][4];
        #pragma unroll
        for (int i = 0; i < 8; ++i)
            #pragma unroll
            for (int j = 0; j < 4; ++j) acc2[i][j] = 0ull;

        #pragma unroll 8
        for (int k = 0; k < FDIM; ++k) {
            const float* ar = xi + k * LDS_ + ty * 8;
            const float* br = xj + k * LDS_ + tx * 8;
            float4 a0 = *(const float4*)ar, a1 = *(const float4*)(ar + 4);
            const ulonglong2* brq = (const ulonglong2*)br;
            ulonglong2 q0 = brq[0], q1 = brq[1];
            u64 b2[4] = {q0.x, q0.y, q1.x, q1.y};
            float a[8] = {a0.x, a0.y, a0.z, a0.w, a1.x, a1.y, a1.z, a1.w};
            u64 ap[8];
            #pragma unroll
            for (int i = 0; i < 8; ++i) PACK_F32X2(ap[i], __float_as_uint(a[i]));
            #pragma unroll
            for (int i = 0; i < 8; ++i)
                #pragma unroll
                for (int j = 0; j < 4; ++j)
                    FMA_F32X2(acc2[i][j], ap[i], b2[j], acc2[i][j]);
        }

        // ---- epilogue: d0-keyed cap-24 list, reg-cached threshold ----
        #pragma unroll
        for (int i = 0; i < 8; ++i) {
            const int row = ty * 8 + i;
            const float sqAi_r = sqAi[row];
            float th = kd[row * CAP + (CAP - 1)];
            #pragma unroll
            for (int j4 = 0; j4 < 4; ++j4) {
                unsigned alo, ahi;
                UNPACK_F32X2(alo, ahi, acc2[i][j4]);
                #pragma unroll
                for (int h = 0; h < 2; ++h) {
                    const int j = 2 * j4 + h;
                    const float av = __uint_as_float(h ? ahi : alo);
                    const int colg = col0 + tx * 8 + j;
                    float d0 = __fadd_rn(__fmaf_rn(-2.f, av, sqAi_r), sqAj[tx * 8 + j]);
                    bool cand = d0 <= th;
                    unsigned m = __ballot_sync(0xffffffffu, cand);
                    if (m) {
                        while (m) {
                            int src = __ffs(m) - 1; m &= m - 1u;
                            float dc = __shfl_sync(0xffffffffu, d0, src);
                            float ac = __shfl_sync(0xffffffffu, av, src);
                            int   cc = __shfl_sync(0xffffffffu, colg, src);
                            int   rr = __shfl_sync(0xffffffffu, row, src);
                            float* kdr = kd + rr * CAP;
                            float* kar = ka + rr * CAP;
                            int*   kir = ki + rr * CAP;
                            float sd = 0.f, sa = 0.f; int si = 0; bool pred = false;
                            if (lane < CAP) {
                                sd = kdr[lane]; sa = kar[lane]; si = kir[lane];
                                pred = (dc < sd) || (dc == sd && cc < si);
                            }
                            unsigned pm = __ballot_sync(0xffffffffu, pred);
                            if (pm) {
                                int pos = __ffs(pm) - 1;
                                __syncwarp();
                                if (lane >= pos && lane < CAP - 1) {
                                    kdr[lane + 1] = sd; kar[lane + 1] = sa; kir[lane + 1] = si;
                                }
                                if (lane == pos) { kdr[pos] = dc; kar[pos] = ac; kir[pos] = cc; }
                                __syncwarp();
                            }
                        }
                        th = kd[row * CAP + (CAP - 1)];   // refresh cached threshold
                    }
                }
            }
        }
    }
    __syncthreads();

    // ---- final phase: rebuild three config lists, majority vote ----
    if (tid < TM) {
        const int row = tid;
        const float* sqBb = g_sqB + batch * NPTS;
        const float* sqCb = g_sqC + batch * NPTS;
        const float sqBi_r = sqBb[row0 + row];
        const float sqCi_r = sqCb[row0 + row];
        float d1v[CAP], d2v[CAP], av[CAP]; int iv[CAP];
        #pragma unroll
        for (int c = 0; c < CAP; ++c) {
            av[c] = ka[row * CAP + c];
            iv[c] = ki[row * CAP + c];
            float sB = sqBb[iv[c]];
            float sC = sqCb[iv[c]];
            d1v[c] = __fadd_rn(__fmaf_rn(-2.f, av[c], sqBi_r), sB);
            d2v[c] = __fmaf_rn(-2.f, av[c], __fadd_rn(sqCi_r, sC));
        }
        int l1[KNN], l2[KNN];
        unsigned used1 = 0, used2 = 0;
        for (int k = 0; k < KNN; ++k) {
            int b1 = -1, b2 = -1;
            #pragma unroll
            for (int c = 0; c < CAP; ++c) {
                if (!(used1 >> c & 1u)) {
                    if (b1 < 0 || d1v[c] < d1v[b1] ||
                        (d1v[c] == d1v[b1] && iv[c] < iv[b1])) b1 = c;
                }
                if (!(used2 >> c & 1u)) {
                    if (b2 < 0 || d2v[c] < d2v[b2] ||
                        (d2v[c] == d2v[b2] && iv[c] < iv[b2])) b2 = c;
                }
            }
            used1 |= 1u << b1; used2 |= 1u << b2;
            l1[k] = iv[b1]; l2[k] = iv[b2];
        }
        for (int k = 0; k < KNN; ++k) {
            int j0 = iv[k], j1 = l1[k], j2 = l2[k];
            int mj = (j0 == j1 || j0 == j2) ? j0 : ((j1 == j2) ? j1 : j0);
            ki[row * CAP + k] = mj;
        }
    }
    __syncthreads();

    // ---- write edge features ----
    const int w = tid >> 5;
    float4* out4 = (float4*)out;
    for (int p = w; p < TM * KNN; p += 8) {
        const int row = p / KNN, k = p % KNN;
        const int ig  = row0 + row;
        const int jg  = ki[row * CAP + k];
        const size_t ob = (((size_t)batch * NPTS + ig) * KNN + k) * 32;
        if (lane < 16) {
            float4 vi = __ldg(&xb4[(size_t)ig * 16 + lane]);
            out4[ob + lane] = vi;
        } else {
            const int q = lane - 16;
            float4 vi = __ldg(&xb4[(size_t)ig * 16 + q]);
            float4 vj = __ldg(&xb4[(size_t)jg * 16 + q]);
            float4 r; r.x = vj.x - vi.x; r.y = vj.y - vi.y; r.z = vj.z - vi.z; r.w = vj.w - vi.w;
            out4[ob + 16 + q] = r;
        }
    }
}

extern "C" void kernel_launch(void* const* d_in, const int* in_sizes, int n_in,
                              void* d_out, int out_size) {
    const float* x = (const float*)d_in[0];
    float* out = (float*)d_out;
    (void)in_sizes; (void)n_in; (void)out_size;

    sqA_kernel<<<(BATCH * NPTS * 32 + 255) / 256, 256>>>(x);
    sqBC_kernel<<<(BATCH * NPTS + 255) / 256, 256>>>(x);

    const size_t smem = (2 * FDIM * LDS_ + 3 * TM * CAP + 2 * TM) * 4;
    cudaFuncSetAttribute(edge_kernel, cudaFuncAttributeMaxDynamicSharedMemorySize, (int)smem);
    edge_kernel<<<BATCH * (NPTS / TM), 256, smem>>>(x, out);
}